// round 11
// baseline (speedup 1.0000x reference)
#include <cuda_runtime.h>
#include <cuda_bf16.h>
#include <cstdint>

#define BATCH 8
#define T 1024
#define D 768
#define F 12288
#define CDIM 48
#define KSEL 3072
#define NPART 16
#define TCHUNK (T / NPART)

// -------- device scratch (allocation-free rule: static __device__ globals) ----
// RULE (hard-learned R3-R7): referenced ONLY from device code. Passing these as
// host-side kernel args yields the host shadow address -> crash (rel_err 1.0).
__device__ float g_part[BATCH * NPART * D];
__device__ float g_ck[BATCH * F];
__device__ int   g_sel[BATCH * KSEL];
__device__ __align__(16) __nv_bfloat16 g_x_hi[(size_t)BATCH * T * D];
__device__ __align__(16) __nv_bfloat16 g_x_lo[(size_t)BATCH * T * D];
__device__ __align__(16) __nv_bfloat16 g_wm_hi[(size_t)F * D];
__device__ __align__(16) __nv_bfloat16 g_wm_lo[(size_t)F * D];
__device__ __align__(16) __nv_bfloat16 g_h_hi[(size_t)BATCH * T * KSEL];
__device__ __align__(16) __nv_bfloat16 g_h_lo[(size_t)BATCH * T * KSEL];
__device__ __align__(16) __nv_bfloat16 g_bc_hi[(size_t)BATCH * D * KSEL];
__device__ __align__(16) __nv_bfloat16 g_bc_lo[(size_t)BATCH * D * KSEL];

// ============================================================================
// PTX helpers (base-target only: cp.async / ldmatrix / mma.sync)
// ============================================================================
__device__ __forceinline__ uint32_t smem_to_u32(const void* p) {
    uint32_t a;
    asm("{ .reg .u64 t; cvta.to.shared.u64 t, %1; cvt.u32.u64 %0, t; }" : "=r"(a) : "l"(p));
    return a;
}
__device__ __forceinline__ void cp_async16(uint32_t saddr, const void* gptr) {
    asm volatile("cp.async.cg.shared.global [%0], [%1], 16;" :: "r"(saddr), "l"(gptr) : "memory");
}
__device__ __forceinline__ void cp_commit() { asm volatile("cp.async.commit_group;" ::: "memory"); }
__device__ __forceinline__ void cp_wait1()  { asm volatile("cp.async.wait_group 1;" ::: "memory"); }

__device__ __forceinline__ void ldm_x4(uint32_t* r, uint32_t addr) {
    asm volatile("ldmatrix.sync.aligned.m8n8.x4.shared.b16 {%0,%1,%2,%3}, [%4];"
                 : "=r"(r[0]), "=r"(r[1]), "=r"(r[2]), "=r"(r[3]) : "r"(addr));
}
__device__ __forceinline__ void mma_bf16(float* c, const uint32_t* a, const uint32_t* b) {
    asm volatile("mma.sync.aligned.m16n8k16.row.col.f32.bf16.bf16.f32 "
                 "{%0,%1,%2,%3}, {%4,%5,%6,%7}, {%8,%9}, {%0,%1,%2,%3};"
                 : "+f"(c[0]), "+f"(c[1]), "+f"(c[2]), "+f"(c[3])
                 : "r"(a[0]), "r"(a[1]), "r"(a[2]), "r"(a[3]), "r"(b[0]), "r"(b[1]));
}
__device__ __forceinline__ uint32_t bf162_as_u32(__nv_bfloat162 v) {
    return *reinterpret_cast<uint32_t*>(&v);
}

// ============================================================================
// K1: partial sequence-mean pool (verified)
// ============================================================================
__global__ void pool_partial_kernel(const float* __restrict__ x) {
    const int b = blockIdx.x >> 4;
    const int s = blockIdx.x & 15;
    const float* xp = x + ((size_t)b * T + (size_t)s * TCHUNK) * D;
    for (int d = threadIdx.x; d < D; d += blockDim.x) {
        float acc = 0.f;
        #pragma unroll 4
        for (int t = 0; t < TCHUNK; t++) acc += xp[(size_t)t * D + d];
        g_part[(size_t)blockIdx.x * D + d] = acc;
    }
}

// ============================================================================
// K2: ck = relu(pooled @ w1^T) @ w2^T (verified)
// ============================================================================
__global__ void __launch_bounds__(1024) ck_kernel(const float* __restrict__ w1,
                                                  const float* __restrict__ w2) {
    const int b = blockIdx.x;
    __shared__ float pooled_s[D];
    __shared__ float tmp_s[CDIM];
    const int tid = threadIdx.x;

    for (int d = tid; d < D; d += blockDim.x) {
        float s = 0.f;
        #pragma unroll
        for (int p = 0; p < NPART; p++) s += g_part[(size_t)(b * NPART + p) * D + d];
        pooled_s[d] = s * (1.0f / (float)T);
    }
    __syncthreads();

    const int wid = tid >> 5, lane = tid & 31;
    for (int c = wid; c < CDIM; c += 32) {
        float s = 0.f;
        for (int d = lane; d < D; d += 32) s += pooled_s[d] * w1[(size_t)c * D + d];
        #pragma unroll
        for (int o = 16; o > 0; o >>= 1) s += __shfl_xor_sync(0xFFFFFFFFu, s, o);
        if (lane == 0) tmp_s[c] = fmaxf(s, 0.f);
    }
    __syncthreads();

    for (int f = tid; f < F; f += blockDim.x) {
        const float* w2r = w2 + (size_t)f * CDIM;
        float s = 0.f;
        #pragma unroll
        for (int c = 0; c < CDIM; c++) s += tmp_s[c] * w2r[c];
        g_ck[b * F + f] = s;
    }
}

// ============================================================================
// K3: exact top-KSEL radix select + deterministic compaction (verified)
// ============================================================================
__global__ void __launch_bounds__(1024) topk_kernel() {
    const int b = blockIdx.x;
    const float* ck = g_ck + b * F;

    __shared__ unsigned hist[256];
    __shared__ unsigned s_prefix, s_remaining;
    __shared__ int s_wcnt_gt[32], s_wcnt_eq[32];
    __shared__ int s_woff_gt[32], s_woff_eq[32];
    __shared__ int s_base_gt, s_base_eq;

    const int tid = threadIdx.x;
    unsigned keys[12];
    #pragma unroll
    for (int i = 0; i < 12; i++) {
        unsigned u = __float_as_uint(ck[i * 1024 + tid]);
        keys[i] = (u & 0x80000000u) ? ~u : (u | 0x80000000u);
    }
    if (tid == 0) { s_prefix = 0u; s_remaining = KSEL; }
    unsigned prefix_mask = 0u;
    __syncthreads();

    for (int pass = 0; pass < 4; pass++) {
        const int shift = 24 - 8 * pass;
        if (tid < 256) hist[tid] = 0u;
        __syncthreads();
        const unsigned prefix = s_prefix;
        #pragma unroll
        for (int i = 0; i < 12; i++) {
            if ((keys[i] & prefix_mask) == prefix)
                atomicAdd(&hist[(keys[i] >> shift) & 255u], 1u);
        }
        __syncthreads();
        if (tid == 0) {
            const unsigned rem = s_remaining;
            unsigned cum = 0u;
            int bin = 255;
            for (; bin > 0; bin--) {
                if (cum + hist[bin] >= rem) break;
                cum += hist[bin];
            }
            s_remaining = rem - cum;
            s_prefix = prefix | ((unsigned)bin << shift);
        }
        prefix_mask |= (0xFFu << shift);
        __syncthreads();
    }

    const unsigned thr = s_prefix;
    const int remaining = (int)s_remaining;
    const int gt_total  = KSEL - remaining;

    if (tid == 0) { s_base_gt = 0; s_base_eq = 0; }
    __syncthreads();

    const int wid = tid >> 5, lane = tid & 31;
    const unsigned lmask = (1u << lane) - 1u;
    for (int i = 0; i < 12; i++) {
        const int idx = i * 1024 + tid;
        const unsigned k = keys[i];
        const bool isgt = (k > thr);
        const bool iseq = (k == thr);
        const unsigned bg = __ballot_sync(0xFFFFFFFFu, isgt);
        const unsigned be = __ballot_sync(0xFFFFFFFFu, iseq);
        if (lane == 0) { s_wcnt_gt[wid] = __popc(bg); s_wcnt_eq[wid] = __popc(be); }
        __syncthreads();
        if (tid == 0) {
            int sg = s_base_gt, se = s_base_eq;
            for (int w = 0; w < 32; w++) {
                s_woff_gt[w] = sg; sg += s_wcnt_gt[w];
                s_woff_eq[w] = se; se += s_wcnt_eq[w];
            }
            s_base_gt = sg; s_base_eq = se;
        }
        __syncthreads();
        if (isgt) {
            const int pos = s_woff_gt[wid] + __popc(bg & lmask);
            g_sel[b * KSEL + pos] = idx;
        } else if (iseq) {
            const int er = s_woff_eq[wid] + __popc(be & lmask);
            if (er < remaining) g_sel[b * KSEL + gt_total + er] = idx;
        }
    }
}

// ============================================================================
// K4: fp32 -> bf16 hi/lo splits (x and w_mfc)
// ============================================================================
__global__ void split_x_kernel(const float* __restrict__ src) {
    const int i = blockIdx.x * blockDim.x + threadIdx.x;
    const int n4 = BATCH * T * D / 4;
    if (i >= n4) return;
    const float4 v = ((const float4*)src)[i];
    const __nv_bfloat162 h0 = __floats2bfloat162_rn(v.x, v.y);
    const __nv_bfloat162 h1 = __floats2bfloat162_rn(v.z, v.w);
    const __nv_bfloat162 l0 = __floats2bfloat162_rn(
        v.x - __bfloat162float(__low2bfloat16(h0)), v.y - __bfloat162float(__high2bfloat16(h0)));
    const __nv_bfloat162 l1 = __floats2bfloat162_rn(
        v.z - __bfloat162float(__low2bfloat16(h1)), v.w - __bfloat162float(__high2bfloat16(h1)));
    ((__nv_bfloat162*)g_x_hi)[2 * i]     = h0;
    ((__nv_bfloat162*)g_x_hi)[2 * i + 1] = h1;
    ((__nv_bfloat162*)g_x_lo)[2 * i]     = l0;
    ((__nv_bfloat162*)g_x_lo)[2 * i + 1] = l1;
}
__global__ void split_wm_kernel(const float* __restrict__ src) {
    const int i = blockIdx.x * blockDim.x + threadIdx.x;
    const int n4 = F * D / 4;
    if (i >= n4) return;
    const float4 v = ((const float4*)src)[i];
    const __nv_bfloat162 h0 = __floats2bfloat162_rn(v.x, v.y);
    const __nv_bfloat162 h1 = __floats2bfloat162_rn(v.z, v.w);
    const __nv_bfloat162 l0 = __floats2bfloat162_rn(
        v.x - __bfloat162float(__low2bfloat16(h0)), v.y - __bfloat162float(__high2bfloat16(h0)));
    const __nv_bfloat162 l1 = __floats2bfloat162_rn(
        v.z - __bfloat162float(__low2bfloat16(h1)), v.w - __bfloat162float(__high2bfloat16(h1)));
    ((__nv_bfloat162*)g_wm_hi)[2 * i]     = h0;
    ((__nv_bfloat162*)g_wm_hi)[2 * i + 1] = h1;
    ((__nv_bfloat162*)g_wm_lo)[2 * i]     = l0;
    ((__nv_bfloat162*)g_wm_lo)[2 * i + 1] = l1;
}

// ============================================================================
// K5: gather+split bc[b][e][j] = w_proj[e][sel[b][j]] (SMEM row cache, verified)
// ============================================================================
__global__ void __launch_bounds__(256) gather_wproj_kernel(const float* __restrict__ wp) {
    __shared__ __nv_bfloat16 rh[F];   // 24576 B
    __shared__ __nv_bfloat16 rl[F];   // 24576 B  (total 48KB static)
    const int e = blockIdx.x;
    const int tid = threadIdx.x;
    const float* row = wp + (size_t)e * F;

    for (int f = tid; f < F; f += 256) {
        const float v = row[f];
        const __nv_bfloat16 h = __float2bfloat16_rn(v);
        rh[f] = h;
        rl[f] = __float2bfloat16_rn(v - __bfloat162float(h));
    }
    __syncthreads();

    for (int b = 0; b < BATCH; b++) {
        const int* sel = g_sel + b * KSEL;
        __nv_bfloat16* bh = g_bc_hi + (size_t)(b * D + e) * KSEL;
        __nv_bfloat16* bl = g_bc_lo + (size_t)(b * D + e) * KSEL;
        for (int j = tid; j < KSEL; j += 256) {
            const int f = __ldg(sel + j);   // coalesced
            bh[j] = rh[f];
            bl[j] = rl[f];
        }
    }
}

// ============================================================================
// HMMA GEMM: C[128(m) x 128(n)] per CTA, bf16 hi/lo 3-pass split, m16n8k16.
// 8 warps = 2(m) x 4(n), warp tile 64x32, full 128x128 coverage.
// 3-STAGE cp.async pipeline with wait_group 1 — two chunk-loads in flight
// under every compute, hiding DRAM latency AND bandwidth jitter.
// R10 lesson: 3*16KB dynamic + 512B static selc = 49664 > 49152 default
// per-block SMEM limit -> launch failed. Fix: opt-in via
// cudaFuncSetAttribute(MaxDynamicSharedMemorySize) in kernel_launch (host
// attribute call: no allocation, no stream op, graph-capture-neutral).
// 2 CTAs/SM x ~49.7KB = ~99KB/SM < 227KB carveout -> occupancy preserved.
// XOR swizzle unit' = unit ^ ((row>>2)&1) -> conflict-free ldmatrix.
//   IS_G1: A = g_x_hi/lo [T,D], B = g_wm_hi/lo gathered via g_sel, K=D,
//          epilogue relu + hi/lo split -> g_h_hi/lo [T,KSEL]
//  !IS_G1: A = g_h_hi/lo [T,KSEL], B = g_bc_hi/lo [D,KSEL] per batch,
//          K=KSEL, fp32 epilogue -> out [T,D]
// ============================================================================
#define A_TILE_B 4096
#define B_TILE_B 4096
#define STAGE_B  16384
#define NSTAGE   3
#define GEMM_SMEM (NSTAGE * STAGE_B)   // 49152 B dynamic (+512 B static selc)

template <bool IS_G1>
__global__ void __launch_bounds__(256, 2) gemm_hmma(float* __restrict__ Of) {
    extern __shared__ __align__(16) char smbuf[];
    __shared__ int selc[128];
    const uint32_t sbase = smem_to_u32(smbuf);
    const int tid = threadIdx.x;
    const int b = blockIdx.z;
    const int n0 = blockIdx.x * 128, m0 = blockIdx.y * 128;

    const int lda  = IS_G1 ? D : KSEL;
    const int ldb  = IS_G1 ? D : KSEL;
    const int Kdim = IS_G1 ? D : KSEL;

    const __nv_bfloat16* Ahi = IS_G1 ? (g_x_hi + (size_t)b * T * D)
                                     : (g_h_hi + (size_t)b * T * KSEL);
    const __nv_bfloat16* Alo = IS_G1 ? (g_x_lo + (size_t)b * T * D)
                                     : (g_h_lo + (size_t)b * T * KSEL);
    const __nv_bfloat16* Bhi = IS_G1 ? g_wm_hi : (g_bc_hi + (size_t)b * D * KSEL);
    const __nv_bfloat16* Blo = IS_G1 ? g_wm_lo : (g_bc_lo + (size_t)b * D * KSEL);

    if (IS_G1) {
        if (tid < 128) selc[tid] = g_sel[b * KSEL + n0 + tid];
        __syncthreads();
    }

    // --- cp.async slots: row r = tid>>1 (0..127), 16B unit u = tid&1 ---
    const int r = tid >> 1, u = tid & 1;
    const uint32_t soff = (uint32_t)(r * 32 + ((u ^ ((r >> 2) & 1)) << 4));
    const int gk = u * 8;
    const int arow = m0 + r;
    const int brow = IS_G1 ? selc[r] : (n0 + r);

    const int nch = Kdim / 16;

    auto load_stage = [&](int stage, int k0) {
        const uint32_t s = sbase + (uint32_t)stage * STAGE_B;
        cp_async16(s + soff, Ahi + (size_t)arow * lda + k0 + gk);
        cp_async16(s + A_TILE_B + soff, Alo + (size_t)arow * lda + k0 + gk);
        cp_async16(s + 2 * A_TILE_B + soff, Bhi + (size_t)brow * ldb + k0 + gk);
        cp_async16(s + 2 * A_TILE_B + B_TILE_B + soff, Blo + (size_t)brow * ldb + k0 + gk);
        cp_commit();
    };

    // --- warp tiling: 8 warps = 2(m) x 4(n), warp tile 64x32 ---
    const int warp = tid >> 5, lane = tid & 31;
    const int wm = warp & 1;          // m base = wm*64
    const int wn = warp >> 1;         // n base = wn*32
    const int lt = lane >> 3, lri = lane & 7;

    const int a_row_l = (lt & 1) * 8 + lri;   // A matrices m0k0,m8k0,m0k8,m8k8
    const int a_ku    = lt >> 1;
    const int b_row_l = (lt >> 1) * 8 + lri;  // B matrices n0k0,n0k8,n8k0,n8k8
    const int b_ku    = lt & 1;

    uint32_t aoff[4];
    #pragma unroll
    for (int mi = 0; mi < 4; mi++) {
        const int ar = wm * 64 + mi * 16 + a_row_l;
        aoff[mi] = (uint32_t)(ar * 32 + ((a_ku ^ ((ar >> 2) & 1)) << 4));
    }
    uint32_t boff[2];
    #pragma unroll
    for (int g = 0; g < 2; g++) {
        const int br = wn * 32 + g * 16 + b_row_l;
        boff[g] = (uint32_t)(2 * A_TILE_B + br * 32 + ((b_ku ^ ((br >> 2) & 1)) << 4));
    }

    float acc[4][4][4];
    #pragma unroll
    for (int mi = 0; mi < 4; mi++)
        #pragma unroll
        for (int ni = 0; ni < 4; ni++)
            #pragma unroll
            for (int q = 0; q < 4; q++) acc[mi][ni][q] = 0.f;

    load_stage(0, 0);
    load_stage(1, 16);

    for (int ch = 0; ch < nch; ch++) {
        cp_wait1();        // stage ch complete (one group may stay in flight)
        __syncthreads();   // stage-ch data visible; stage (ch+2)%3 reads done
        if (ch + 2 < nch) load_stage((ch + 2) % NSTAGE, (ch + 2) * 16);
        else cp_commit();  // empty group keeps wait_group numbering sound

        const uint32_t s = sbase + (uint32_t)(ch % NSTAGE) * STAGE_B;
        uint32_t ah[4][4], al[4][4], bh[2][4], bl[2][4];
        #pragma unroll
        for (int mi = 0; mi < 4; mi++) {
            ldm_x4(ah[mi], s + aoff[mi]);
            ldm_x4(al[mi], s + A_TILE_B + aoff[mi]);
        }
        #pragma unroll
        for (int g = 0; g < 2; g++) {
            ldm_x4(bh[g], s + boff[g]);
            ldm_x4(bl[g], s + B_TILE_B + boff[g]);
        }

        #pragma unroll
        for (int mi = 0; mi < 4; mi++)
            #pragma unroll
            for (int ni = 0; ni < 4; ni++) {
                const uint32_t* ph = &bh[ni >> 1][(ni & 1) * 2];
                const uint32_t* pl = &bl[ni >> 1][(ni & 1) * 2];
                mma_bf16(acc[mi][ni], ah[mi], ph);  // hi*hi
                mma_bf16(acc[mi][ni], ah[mi], pl);  // hi*lo
                mma_bf16(acc[mi][ni], al[mi], ph);  // lo*hi
            }
    }

    // --- epilogue ---
    const int erow = lane >> 2, ecol = (lane & 3) * 2;
    #pragma unroll
    for (int mi = 0; mi < 4; mi++)
        #pragma unroll
        for (int ni = 0; ni < 4; ni++) {
            const int row = m0 + wm * 64 + mi * 16 + erow;
            const int col = n0 + wn * 32 + ni * 8 + ecol;
            #pragma unroll
            for (int h = 0; h < 2; h++) {   // c0/c1 at row, c2/c3 at row+8
                const int rr = row + h * 8;
                float f0 = acc[mi][ni][h * 2 + 0];
                float f1 = acc[mi][ni][h * 2 + 1];
                if (IS_G1) {
                    f0 = fmaxf(f0, 0.f); f1 = fmaxf(f1, 0.f);
                    const __nv_bfloat162 hp = __floats2bfloat162_rn(f0, f1);
                    const __nv_bfloat162 lp = __floats2bfloat162_rn(
                        f0 - __bfloat162float(__low2bfloat16(hp)),
                        f1 - __bfloat162float(__high2bfloat16(hp)));
                    __nv_bfloat16* hh = g_h_hi + (size_t)b * T * KSEL;
                    __nv_bfloat16* hl = g_h_lo + (size_t)b * T * KSEL;
                    *(uint32_t*)(hh + (size_t)rr * KSEL + col) = bf162_as_u32(hp);
                    *(uint32_t*)(hl + (size_t)rr * KSEL + col) = bf162_as_u32(lp);
                } else {
                    float2 v; v.x = f0; v.y = f1;
                    *(float2*)(Of + ((size_t)b * T + rr) * D + col) = v;
                }
            }
        }
}

// ============================================================================
extern "C" void kernel_launch(void* const* d_in, const int* in_sizes, int n_in,
                              void* d_out, int out_size) {
    const float* x      = (const float*)d_in[0];
    const float* w1     = (const float*)d_in[1];
    const float* w2     = (const float*)d_in[2];
    const float* w_mfc  = (const float*)d_in[3];
    const float* w_proj = (const float*)d_in[4];
    float* out = (float*)d_out;

    // Opt in to >48KB dynamic SMEM for the GEMM kernels (R10 failed without
    // this: 49152 dynamic + 512 static selc > 49152 default per-block limit).
    // Host attribute call — no allocation, no stream op, capture-neutral.
    static bool attr_done = false;
    if (!attr_done) {
        cudaFuncSetAttribute(gemm_hmma<true>,
                             cudaFuncAttributeMaxDynamicSharedMemorySize, GEMM_SMEM);
        cudaFuncSetAttribute(gemm_hmma<false>,
                             cudaFuncAttributeMaxDynamicSharedMemorySize, GEMM_SMEM);
        attr_done = true;
    }

    pool_partial_kernel<<<BATCH * NPART, 256>>>(x);
    ck_kernel<<<BATCH, 1024>>>(w1, w2);
    topk_kernel<<<BATCH, 1024>>>();
    split_x_kernel<<<(BATCH * T * D / 4 + 255) / 256, 256>>>(x);
    split_wm_kernel<<<(F * D / 4 + 255) / 256, 256>>>(w_mfc);
    gather_wproj_kernel<<<D, 256>>>(w_proj);

    // GEMM1: h = relu(x @ wm_sel^T), gathered-N, relu + hi/lo split epilogue
    gemm_hmma<true><<<dim3(KSEL / 128, T / 128, BATCH), 256, GEMM_SMEM>>>(nullptr);

    // GEMM2: out = h @ bc^T, fp32 epilogue (d_out is a real device pointer)
    gemm_hmma<false><<<dim3(D / 128, T / 128, BATCH), 256, GEMM_SMEM>>>(out);
}

// round 12
// speedup vs baseline: 1.3344x; 1.3344x over previous
#include <cuda_runtime.h>
#include <cuda_bf16.h>
#include <cuda_fp16.h>
#include <cstdint>

#define BATCH 8
#define T 1024
#define D 768
#define F 12288
#define CDIM 48
#define KSEL 3072
#define NPART 16
#define TCHUNK (T / NPART)

// -------- device scratch (allocation-free rule: static __device__ globals) ----
// RULE (hard-learned R3-R7): referenced ONLY from device code. Passing these as
// host-side kernel args yields the host shadow address -> crash (rel_err 1.0).
__device__ float g_part[BATCH * NPART * D];
__device__ float g_ck[BATCH * F];
__device__ int   g_sel[BATCH * KSEL];
__device__ __align__(16) __half g_x_h[(size_t)BATCH * T * D];     // fp16(x)
__device__ __align__(16) __half g_wm_hi[(size_t)F * D];           // fp16 split of w_mfc
__device__ __align__(16) __half g_wm_lo[(size_t)F * D];
__device__ __align__(16) __half g_h[(size_t)BATCH * T * KSEL];    // fp16(relu(h))
__device__ __align__(16) __half g_bc_hi[(size_t)BATCH * D * KSEL];
__device__ __align__(16) __half g_bc_lo[(size_t)BATCH * D * KSEL];

// ============================================================================
// PTX helpers (base-target only: cp.async / ldmatrix / mma.sync)
// ============================================================================
__device__ __forceinline__ uint32_t smem_to_u32(const void* p) {
    uint32_t a;
    asm("{ .reg .u64 t; cvta.to.shared.u64 t, %1; cvt.u32.u64 %0, t; }" : "=r"(a) : "l"(p));
    return a;
}
__device__ __forceinline__ void cp_async16(uint32_t saddr, const void* gptr) {
    asm volatile("cp.async.cg.shared.global [%0], [%1], 16;" :: "r"(saddr), "l"(gptr) : "memory");
}
__device__ __forceinline__ void cp_commit() { asm volatile("cp.async.commit_group;" ::: "memory"); }
__device__ __forceinline__ void cp_wait0()  { asm volatile("cp.async.wait_group 0;" ::: "memory"); }

__device__ __forceinline__ void ldm_x4(uint32_t* r, uint32_t addr) {
    asm volatile("ldmatrix.sync.aligned.m8n8.x4.shared.b16 {%0,%1,%2,%3}, [%4];"
                 : "=r"(r[0]), "=r"(r[1]), "=r"(r[2]), "=r"(r[3]) : "r"(addr));
}
__device__ __forceinline__ void mma_f16(float* c, const uint32_t* a, const uint32_t* b) {
    asm volatile("mma.sync.aligned.m16n8k16.row.col.f32.f16.f16.f32 "
                 "{%0,%1,%2,%3}, {%4,%5,%6,%7}, {%8,%9}, {%0,%1,%2,%3};"
                 : "+f"(c[0]), "+f"(c[1]), "+f"(c[2]), "+f"(c[3])
                 : "r"(a[0]), "r"(a[1]), "r"(a[2]), "r"(a[3]), "r"(b[0]), "r"(b[1]));
}
__device__ __forceinline__ uint32_t half2_as_u32(__half2 v) {
    return *reinterpret_cast<uint32_t*>(&v);
}

// ============================================================================
// K1: partial sequence-mean pool (verified)
// ============================================================================
__global__ void pool_partial_kernel(const float* __restrict__ x) {
    const int b = blockIdx.x >> 4;
    const int s = blockIdx.x & 15;
    const float* xp = x + ((size_t)b * T + (size_t)s * TCHUNK) * D;
    for (int d = threadIdx.x; d < D; d += blockDim.x) {
        float acc = 0.f;
        #pragma unroll 4
        for (int t = 0; t < TCHUNK; t++) acc += xp[(size_t)t * D + d];
        g_part[(size_t)blockIdx.x * D + d] = acc;
    }
}

// ============================================================================
// K2: ck = relu(pooled @ w1^T) @ w2^T (verified)
// ============================================================================
__global__ void __launch_bounds__(1024) ck_kernel(const float* __restrict__ w1,
                                                  const float* __restrict__ w2) {
    const int b = blockIdx.x;
    __shared__ float pooled_s[D];
    __shared__ float tmp_s[CDIM];
    const int tid = threadIdx.x;

    for (int d = tid; d < D; d += blockDim.x) {
        float s = 0.f;
        #pragma unroll
        for (int p = 0; p < NPART; p++) s += g_part[(size_t)(b * NPART + p) * D + d];
        pooled_s[d] = s * (1.0f / (float)T);
    }
    __syncthreads();

    const int wid = tid >> 5, lane = tid & 31;
    for (int c = wid; c < CDIM; c += 32) {
        float s = 0.f;
        for (int d = lane; d < D; d += 32) s += pooled_s[d] * w1[(size_t)c * D + d];
        #pragma unroll
        for (int o = 16; o > 0; o >>= 1) s += __shfl_xor_sync(0xFFFFFFFFu, s, o);
        if (lane == 0) tmp_s[c] = fmaxf(s, 0.f);
    }
    __syncthreads();

    for (int f = tid; f < F; f += blockDim.x) {
        const float* w2r = w2 + (size_t)f * CDIM;
        float s = 0.f;
        #pragma unroll
        for (int c = 0; c < CDIM; c++) s += tmp_s[c] * w2r[c];
        g_ck[b * F + f] = s;
    }
}

// ============================================================================
// K3: exact top-KSEL radix select + deterministic compaction (verified)
// ============================================================================
__global__ void __launch_bounds__(1024) topk_kernel() {
    const int b = blockIdx.x;
    const float* ck = g_ck + b * F;

    __shared__ unsigned hist[256];
    __shared__ unsigned s_prefix, s_remaining;
    __shared__ int s_wcnt_gt[32], s_wcnt_eq[32];
    __shared__ int s_woff_gt[32], s_woff_eq[32];
    __shared__ int s_base_gt, s_base_eq;

    const int tid = threadIdx.x;
    unsigned keys[12];
    #pragma unroll
    for (int i = 0; i < 12; i++) {
        unsigned u = __float_as_uint(ck[i * 1024 + tid]);
        keys[i] = (u & 0x80000000u) ? ~u : (u | 0x80000000u);
    }
    if (tid == 0) { s_prefix = 0u; s_remaining = KSEL; }
    unsigned prefix_mask = 0u;
    __syncthreads();

    for (int pass = 0; pass < 4; pass++) {
        const int shift = 24 - 8 * pass;
        if (tid < 256) hist[tid] = 0u;
        __syncthreads();
        const unsigned prefix = s_prefix;
        #pragma unroll
        for (int i = 0; i < 12; i++) {
            if ((keys[i] & prefix_mask) == prefix)
                atomicAdd(&hist[(keys[i] >> shift) & 255u], 1u);
        }
        __syncthreads();
        if (tid == 0) {
            const unsigned rem = s_remaining;
            unsigned cum = 0u;
            int bin = 255;
            for (; bin > 0; bin--) {
                if (cum + hist[bin] >= rem) break;
                cum += hist[bin];
            }
            s_remaining = rem - cum;
            s_prefix = prefix | ((unsigned)bin << shift);
        }
        prefix_mask |= (0xFFu << shift);
        __syncthreads();
    }

    const unsigned thr = s_prefix;
    const int remaining = (int)s_remaining;
    const int gt_total  = KSEL - remaining;

    if (tid == 0) { s_base_gt = 0; s_base_eq = 0; }
    __syncthreads();

    const int wid = tid >> 5, lane = tid & 31;
    const unsigned lmask = (1u << lane) - 1u;
    for (int i = 0; i < 12; i++) {
        const int idx = i * 1024 + tid;
        const unsigned k = keys[i];
        const bool isgt = (k > thr);
        const bool iseq = (k == thr);
        const unsigned bg = __ballot_sync(0xFFFFFFFFu, isgt);
        const unsigned be = __ballot_sync(0xFFFFFFFFu, iseq);
        if (lane == 0) { s_wcnt_gt[wid] = __popc(bg); s_wcnt_eq[wid] = __popc(be); }
        __syncthreads();
        if (tid == 0) {
            int sg = s_base_gt, se = s_base_eq;
            for (int w = 0; w < 32; w++) {
                s_woff_gt[w] = sg; sg += s_wcnt_gt[w];
                s_woff_eq[w] = se; se += s_wcnt_eq[w];
            }
            s_base_gt = sg; s_base_eq = se;
        }
        __syncthreads();
        if (isgt) {
            const int pos = s_woff_gt[wid] + __popc(bg & lmask);
            g_sel[b * KSEL + pos] = idx;
        } else if (iseq) {
            const int er = s_woff_eq[wid] + __popc(be & lmask);
            if (er < remaining) g_sel[b * KSEL + gt_total + er] = idx;
        }
    }
}

// ============================================================================
// K4a: x -> fp16 (A side of GEMM1 needs NO split: error lives in dropped
// e_x * wm term, ~2.8e-4 RMS)
// ============================================================================
__global__ void conv_x_kernel(const float* __restrict__ src) {
    const int i = blockIdx.x * blockDim.x + threadIdx.x;
    const int n4 = BATCH * T * D / 4;
    if (i >= n4) return;
    const float4 v = ((const float4*)src)[i];
    __half2 h0 = __floats2half2_rn(v.x, v.y);
    __half2 h1 = __floats2half2_rn(v.z, v.w);
    ((__half2*)g_x_h)[2 * i]     = h0;
    ((__half2*)g_x_h)[2 * i + 1] = h1;
}

// ============================================================================
// K4b: w_mfc -> fp16 hi/lo split (B side of GEMM1: hi+lo reconstructs w to
// ~2^-22, so B contributes no meaningful error)
// ============================================================================
__global__ void split_wm_kernel(const float* __restrict__ src) {
    const int i = blockIdx.x * blockDim.x + threadIdx.x;
    const int n4 = F * D / 4;
    if (i >= n4) return;
    const float4 v = ((const float4*)src)[i];
    const __half hx = __float2half_rn(v.x), hy = __float2half_rn(v.y);
    const __half hz = __float2half_rn(v.z), hw = __float2half_rn(v.w);
    __half2 hi0; hi0.x = hx; hi0.y = hy;
    __half2 hi1; hi1.x = hz; hi1.y = hw;
    __half2 lo0 = __floats2half2_rn(v.x - __half2float(hx), v.y - __half2float(hy));
    __half2 lo1 = __floats2half2_rn(v.z - __half2float(hz), v.w - __half2float(hw));
    ((__half2*)g_wm_hi)[2 * i]     = hi0;
    ((__half2*)g_wm_hi)[2 * i + 1] = hi1;
    ((__half2*)g_wm_lo)[2 * i]     = lo0;
    ((__half2*)g_wm_lo)[2 * i + 1] = lo1;
}

// ============================================================================
// K5: gather+split bc[b][e][j] = w_proj[e][sel[b][j]] (fp16 hi/lo; SMEM row
// cache serving all 8 batches — verified pattern from R9)
// ============================================================================
__global__ void __launch_bounds__(256) gather_wproj_kernel(const float* __restrict__ wp) {
    __shared__ __half rh[F];   // 24576 B
    __shared__ __half rl[F];   // 24576 B  (total 48KB static)
    const int e = blockIdx.x;
    const int tid = threadIdx.x;
    const float* row = wp + (size_t)e * F;

    for (int f = tid; f < F; f += 256) {
        const float v = row[f];
        const __half h = __float2half_rn(v);
        rh[f] = h;
        rl[f] = __float2half_rn(v - __half2float(h));
    }
    __syncthreads();

    for (int b = 0; b < BATCH; b++) {
        const int* sel = g_sel + b * KSEL;
        __half* bh = g_bc_hi + (size_t)(b * D + e) * KSEL;
        __half* bl = g_bc_lo + (size_t)(b * D + e) * KSEL;
        for (int j = tid; j < KSEL; j += 256) {
            const int f = __ldg(sel + j);   // coalesced
            bh[j] = rh[f];
            bl[j] = rl[f];
        }
    }
}

// ============================================================================
// HMMA GEMM: C[128(m) x 128(n)] per CTA = A_fp16[128xK] @ (B_hi+B_lo)[128xK]^T
// 2 MMAs per fragment (ah*bh + ah*bl) — R11 lesson: legacy mma.sync on sm_103
// is ISSUE-RATE-bound (~512 MAC/cyc/SM); bandwidth (R9) and latency (R11)
// tuning were null. Cutting 3 MMAs -> 2 cuts tensor time by 1/3; A needs no
// lo tile so loads shrink 25% too.
// 8 warps = 2(m) x 4(n), warp tile 64x32, full coverage. 2-stage cp.async
// (R9 best-known), static smem 2 x 12KB = 24KB, no attribute, 2 CTAs/SM.
// XOR swizzle unit' = unit ^ ((row>>2)&1) -> conflict-free ldmatrix.
//   IS_G1: A = g_x_h [T,D], B = g_wm_hi/lo gathered via g_sel, K=D,
//          epilogue relu -> fp16 g_h [T,KSEL]
//  !IS_G1: A = g_h [T,KSEL], B = g_bc_hi/lo [D,KSEL] per batch, K=KSEL,
//          fp32 epilogue -> out [T,D]
// ============================================================================
#define A_TILE_B 4096
#define B_TILE_B 4096
#define STAGE_B  12288   // Ahi 4K | Bhi 4K | Blo 4K

template <bool IS_G1>
__global__ void __launch_bounds__(256, 2) gemm_hmma(float* __restrict__ Of) {
    __shared__ __align__(16) char smbuf[2 * STAGE_B];   // 24 KB static
    __shared__ int selc[128];
    const uint32_t sbase = smem_to_u32(smbuf);
    const int tid = threadIdx.x;
    const int b = blockIdx.z;
    const int n0 = blockIdx.x * 128, m0 = blockIdx.y * 128;

    const int lda  = IS_G1 ? D : KSEL;
    const int ldb  = IS_G1 ? D : KSEL;
    const int Kdim = IS_G1 ? D : KSEL;

    const __half* A   = IS_G1 ? (g_x_h + (size_t)b * T * D)
                              : (g_h + (size_t)b * T * KSEL);
    const __half* Bhi = IS_G1 ? g_wm_hi : (g_bc_hi + (size_t)b * D * KSEL);
    const __half* Blo = IS_G1 ? g_wm_lo : (g_bc_lo + (size_t)b * D * KSEL);

    if (IS_G1) {
        if (tid < 128) selc[tid] = g_sel[b * KSEL + n0 + tid];
        __syncthreads();
    }

    // --- cp.async slots: row r = tid>>1 (0..127), 16B unit u = tid&1 ---
    const int r = tid >> 1, u = tid & 1;
    const uint32_t soff = (uint32_t)(r * 32 + ((u ^ ((r >> 2) & 1)) << 4));
    const int gk = u * 8;
    const int arow = m0 + r;
    const int brow = IS_G1 ? selc[r] : (n0 + r);

    const int nch = Kdim / 16;

    auto load_stage = [&](int stage, int k0) {
        const uint32_t s = sbase + (uint32_t)stage * STAGE_B;
        cp_async16(s + soff, A + (size_t)arow * lda + k0 + gk);
        cp_async16(s + A_TILE_B + soff, Bhi + (size_t)brow * ldb + k0 + gk);
        cp_async16(s + A_TILE_B + B_TILE_B + soff, Blo + (size_t)brow * ldb + k0 + gk);
        cp_commit();
    };

    // --- warp tiling: 8 warps = 2(m) x 4(n), warp tile 64x32 ---
    const int warp = tid >> 5, lane = tid & 31;
    const int wm = warp & 1;          // m base = wm*64
    const int wn = warp >> 1;         // n base = wn*32
    const int lt = lane >> 3, lri = lane & 7;

    const int a_row_l = (lt & 1) * 8 + lri;   // A matrices m0k0,m8k0,m0k8,m8k8
    const int a_ku    = lt >> 1;
    const int b_row_l = (lt >> 1) * 8 + lri;  // B matrices n0k0,n0k8,n8k0,n8k8
    const int b_ku    = lt & 1;

    uint32_t aoff[4];
    #pragma unroll
    for (int mi = 0; mi < 4; mi++) {
        const int ar = wm * 64 + mi * 16 + a_row_l;
        aoff[mi] = (uint32_t)(ar * 32 + ((a_ku ^ ((ar >> 2) & 1)) << 4));
    }
    uint32_t boff[2];
    #pragma unroll
    for (int g = 0; g < 2; g++) {
        const int br = wn * 32 + g * 16 + b_row_l;
        boff[g] = (uint32_t)(A_TILE_B + br * 32 + ((b_ku ^ ((br >> 2) & 1)) << 4));
    }

    float acc[4][4][4];
    #pragma unroll
    for (int mi = 0; mi < 4; mi++)
        #pragma unroll
        for (int ni = 0; ni < 4; ni++)
            #pragma unroll
            for (int q = 0; q < 4; q++) acc[mi][ni][q] = 0.f;

    load_stage(0, 0);

    for (int ch = 0; ch < nch; ch++) {
        cp_wait0();
        __syncthreads();   // stage-ch data visible; prior iteration's reads done
        if (ch + 1 < nch) load_stage((ch + 1) & 1, (ch + 1) * 16);

        const uint32_t s = sbase + (uint32_t)(ch & 1) * STAGE_B;
        uint32_t ah[4][4], bh[2][4], bl[2][4];
        #pragma unroll
        for (int mi = 0; mi < 4; mi++) ldm_x4(ah[mi], s + aoff[mi]);
        #pragma unroll
        for (int g = 0; g < 2; g++) {
            ldm_x4(bh[g], s + boff[g]);
            ldm_x4(bl[g], s + B_TILE_B + boff[g]);
        }

        #pragma unroll
        for (int mi = 0; mi < 4; mi++)
            #pragma unroll
            for (int ni = 0; ni < 4; ni++) {
                const uint32_t* ph = &bh[ni >> 1][(ni & 1) * 2];
                const uint32_t* pl = &bl[ni >> 1][(ni & 1) * 2];
                mma_f16(acc[mi][ni], ah[mi], ph);  // A * B_hi
                mma_f16(acc[mi][ni], ah[mi], pl);  // A * B_lo
            }
    }

    // --- epilogue ---
    const int erow = lane >> 2, ecol = (lane & 3) * 2;
    #pragma unroll
    for (int mi = 0; mi < 4; mi++)
        #pragma unroll
        for (int ni = 0; ni < 4; ni++) {
            const int row = m0 + wm * 64 + mi * 16 + erow;
            const int col = n0 + wn * 32 + ni * 8 + ecol;
            #pragma unroll
            for (int h = 0; h < 2; h++) {   // c0/c1 at row, c2/c3 at row+8
                const int rr = row + h * 8;
                float f0 = acc[mi][ni][h * 2 + 0];
                float f1 = acc[mi][ni][h * 2 + 1];
                if (IS_G1) {
                    f0 = fmaxf(f0, 0.f); f1 = fmaxf(f1, 0.f);
                    const __half2 hp = __floats2half2_rn(f0, f1);
                    __half* hh = g_h + (size_t)b * T * KSEL;
                    *(uint32_t*)(hh + (size_t)rr * KSEL + col) = half2_as_u32(hp);
                } else {
                    float2 v; v.x = f0; v.y = f1;
                    *(float2*)(Of + ((size_t)b * T + rr) * D + col) = v;
                }
            }
        }
}

// ============================================================================
extern "C" void kernel_launch(void* const* d_in, const int* in_sizes, int n_in,
                              void* d_out, int out_size) {
    const float* x      = (const float*)d_in[0];
    const float* w1     = (const float*)d_in[1];
    const float* w2     = (const float*)d_in[2];
    const float* w_mfc  = (const float*)d_in[3];
    const float* w_proj = (const float*)d_in[4];
    float* out = (float*)d_out;

    pool_partial_kernel<<<BATCH * NPART, 256>>>(x);
    ck_kernel<<<BATCH, 1024>>>(w1, w2);
    topk_kernel<<<BATCH, 1024>>>();
    conv_x_kernel<<<(BATCH * T * D / 4 + 255) / 256, 256>>>(x);
    split_wm_kernel<<<(F * D / 4 + 255) / 256, 256>>>(w_mfc);
    gather_wproj_kernel<<<D, 256>>>(w_proj);

    // GEMM1: h = relu(x_fp16 @ (wm_hi+wm_lo)_sel^T), relu -> fp16 h
    gemm_hmma<true><<<dim3(KSEL / 128, T / 128, BATCH), 256>>>(nullptr);

    // GEMM2: out = h_fp16 @ (bc_hi+bc_lo)^T, fp32 epilogue
    gemm_hmma<false><<<dim3(D / 128, T / 128, BATCH), 256>>>(out);
}

// round 13
// speedup vs baseline: 1.5923x; 1.1933x over previous
#include <cuda_runtime.h>
#include <cuda_bf16.h>
#include <cuda_fp16.h>
#include <cstdint>

#define BATCH 8
#define T 1024
#define D 768
#define F 12288
#define CDIM 48
#define KSEL 3072
#define NPART 16
#define TCHUNK (T / NPART)

// -------- device scratch (allocation-free rule: static __device__ globals) ----
// RULE (hard-learned R3-R7): referenced ONLY from device code. Passing these as
// host-side kernel args yields the host shadow address -> crash (rel_err 1.0).
__device__ float g_part[BATCH * NPART * D];
__device__ float g_ck[BATCH * F];
__device__ int   g_sel[BATCH * KSEL];
__device__ __align__(16) __half g_x_h[(size_t)BATCH * T * D];     // fp16(x)
__device__ __align__(16) __half g_wm_h[(size_t)F * D];            // fp16(w_mfc)
__device__ __align__(16) __half g_h[(size_t)BATCH * T * KSEL];    // fp16(relu(h))
__device__ __align__(16) __half g_bc[(size_t)BATCH * D * KSEL];   // fp16 gathered w_proj

// ============================================================================
// PTX helpers (base-target only: cp.async / ldmatrix / mma.sync)
// ============================================================================
__device__ __forceinline__ uint32_t smem_to_u32(const void* p) {
    uint32_t a;
    asm("{ .reg .u64 t; cvta.to.shared.u64 t, %1; cvt.u32.u64 %0, t; }" : "=r"(a) : "l"(p));
    return a;
}
__device__ __forceinline__ void cp_async16(uint32_t saddr, const void* gptr) {
    asm volatile("cp.async.cg.shared.global [%0], [%1], 16;" :: "r"(saddr), "l"(gptr) : "memory");
}
__device__ __forceinline__ void cp_commit() { asm volatile("cp.async.commit_group;" ::: "memory"); }
__device__ __forceinline__ void cp_wait0()  { asm volatile("cp.async.wait_group 0;" ::: "memory"); }

__device__ __forceinline__ void ldm_x4(uint32_t* r, uint32_t addr) {
    asm volatile("ldmatrix.sync.aligned.m8n8.x4.shared.b16 {%0,%1,%2,%3}, [%4];"
                 : "=r"(r[0]), "=r"(r[1]), "=r"(r[2]), "=r"(r[3]) : "r"(addr));
}
__device__ __forceinline__ void mma_f16(float* c, const uint32_t* a, const uint32_t* b) {
    asm volatile("mma.sync.aligned.m16n8k16.row.col.f32.f16.f16.f32 "
                 "{%0,%1,%2,%3}, {%4,%5,%6,%7}, {%8,%9}, {%0,%1,%2,%3};"
                 : "+f"(c[0]), "+f"(c[1]), "+f"(c[2]), "+f"(c[3])
                 : "r"(a[0]), "r"(a[1]), "r"(a[2]), "r"(a[3]), "r"(b[0]), "r"(b[1]));
}
__device__ __forceinline__ uint32_t half2_as_u32(__half2 v) {
    return *reinterpret_cast<uint32_t*>(&v);
}

// ============================================================================
// K1: partial sequence-mean pool (verified)
// ============================================================================
__global__ void pool_partial_kernel(const float* __restrict__ x) {
    const int b = blockIdx.x >> 4;
    const int s = blockIdx.x & 15;
    const float* xp = x + ((size_t)b * T + (size_t)s * TCHUNK) * D;
    for (int d = threadIdx.x; d < D; d += blockDim.x) {
        float acc = 0.f;
        #pragma unroll 4
        for (int t = 0; t < TCHUNK; t++) acc += xp[(size_t)t * D + d];
        g_part[(size_t)blockIdx.x * D + d] = acc;
    }
}

// ============================================================================
// K2: ck = relu(pooled @ w1^T) @ w2^T (verified)
// ============================================================================
__global__ void __launch_bounds__(1024) ck_kernel(const float* __restrict__ w1,
                                                  const float* __restrict__ w2) {
    const int b = blockIdx.x;
    __shared__ float pooled_s[D];
    __shared__ float tmp_s[CDIM];
    const int tid = threadIdx.x;

    for (int d = tid; d < D; d += blockDim.x) {
        float s = 0.f;
        #pragma unroll
        for (int p = 0; p < NPART; p++) s += g_part[(size_t)(b * NPART + p) * D + d];
        pooled_s[d] = s * (1.0f / (float)T);
    }
    __syncthreads();

    const int wid = tid >> 5, lane = tid & 31;
    for (int c = wid; c < CDIM; c += 32) {
        float s = 0.f;
        for (int d = lane; d < D; d += 32) s += pooled_s[d] * w1[(size_t)c * D + d];
        #pragma unroll
        for (int o = 16; o > 0; o >>= 1) s += __shfl_xor_sync(0xFFFFFFFFu, s, o);
        if (lane == 0) tmp_s[c] = fmaxf(s, 0.f);
    }
    __syncthreads();

    for (int f = tid; f < F; f += blockDim.x) {
        const float* w2r = w2 + (size_t)f * CDIM;
        float s = 0.f;
        #pragma unroll
        for (int c = 0; c < CDIM; c++) s += tmp_s[c] * w2r[c];
        g_ck[b * F + f] = s;
    }
}

// ============================================================================
// K3: exact top-KSEL radix select + deterministic compaction (verified)
// ============================================================================
__global__ void __launch_bounds__(1024) topk_kernel() {
    const int b = blockIdx.x;
    const float* ck = g_ck + b * F;

    __shared__ unsigned hist[256];
    __shared__ unsigned s_prefix, s_remaining;
    __shared__ int s_wcnt_gt[32], s_wcnt_eq[32];
    __shared__ int s_woff_gt[32], s_woff_eq[32];
    __shared__ int s_base_gt, s_base_eq;

    const int tid = threadIdx.x;
    unsigned keys[12];
    #pragma unroll
    for (int i = 0; i < 12; i++) {
        unsigned u = __float_as_uint(ck[i * 1024 + tid]);
        keys[i] = (u & 0x80000000u) ? ~u : (u | 0x80000000u);
    }
    if (tid == 0) { s_prefix = 0u; s_remaining = KSEL; }
    unsigned prefix_mask = 0u;
    __syncthreads();

    for (int pass = 0; pass < 4; pass++) {
        const int shift = 24 - 8 * pass;
        if (tid < 256) hist[tid] = 0u;
        __syncthreads();
        const unsigned prefix = s_prefix;
        #pragma unroll
        for (int i = 0; i < 12; i++) {
            if ((keys[i] & prefix_mask) == prefix)
                atomicAdd(&hist[(keys[i] >> shift) & 255u], 1u);
        }
        __syncthreads();
        if (tid == 0) {
            const unsigned rem = s_remaining;
            unsigned cum = 0u;
            int bin = 255;
            for (; bin > 0; bin--) {
                if (cum + hist[bin] >= rem) break;
                cum += hist[bin];
            }
            s_remaining = rem - cum;
            s_prefix = prefix | ((unsigned)bin << shift);
        }
        prefix_mask |= (0xFFu << shift);
        __syncthreads();
    }

    const unsigned thr = s_prefix;
    const int remaining = (int)s_remaining;
    const int gt_total  = KSEL - remaining;

    if (tid == 0) { s_base_gt = 0; s_base_eq = 0; }
    __syncthreads();

    const int wid = tid >> 5, lane = tid & 31;
    const unsigned lmask = (1u << lane) - 1u;
    for (int i = 0; i < 12; i++) {
        const int idx = i * 1024 + tid;
        const unsigned k = keys[i];
        const bool isgt = (k > thr);
        const bool iseq = (k == thr);
        const unsigned bg = __ballot_sync(0xFFFFFFFFu, isgt);
        const unsigned be = __ballot_sync(0xFFFFFFFFu, iseq);
        if (lane == 0) { s_wcnt_gt[wid] = __popc(bg); s_wcnt_eq[wid] = __popc(be); }
        __syncthreads();
        if (tid == 0) {
            int sg = s_base_gt, se = s_base_eq;
            for (int w = 0; w < 32; w++) {
                s_woff_gt[w] = sg; sg += s_wcnt_gt[w];
                s_woff_eq[w] = se; se += s_wcnt_eq[w];
            }
            s_base_gt = sg; s_base_eq = se;
        }
        __syncthreads();
        if (isgt) {
            const int pos = s_woff_gt[wid] + __popc(bg & lmask);
            g_sel[b * KSEL + pos] = idx;
        } else if (iseq) {
            const int er = s_woff_eq[wid] + __popc(be & lmask);
            if (er < remaining) g_sel[b * KSEL + gt_total + er] = idx;
        }
    }
}

// ============================================================================
// K4a: x -> fp16
// ============================================================================
__global__ void conv_x_kernel(const float* __restrict__ src) {
    const int i = blockIdx.x * blockDim.x + threadIdx.x;
    const int n4 = BATCH * T * D / 4;
    if (i >= n4) return;
    const float4 v = ((const float4*)src)[i];
    ((__half2*)g_x_h)[2 * i]     = __floats2half2_rn(v.x, v.y);
    ((__half2*)g_x_h)[2 * i + 1] = __floats2half2_rn(v.z, v.w);
}

// ============================================================================
// K4b: w_mfc -> fp16
// ============================================================================
__global__ void conv_wm_kernel(const float* __restrict__ src) {
    const int i = blockIdx.x * blockDim.x + threadIdx.x;
    const int n4 = F * D / 4;
    if (i >= n4) return;
    const float4 v = ((const float4*)src)[i];
    ((__half2*)g_wm_h)[2 * i]     = __floats2half2_rn(v.x, v.y);
    ((__half2*)g_wm_h)[2 * i + 1] = __floats2half2_rn(v.z, v.w);
}

// ============================================================================
// K5: gather bc[b][e][j] = fp16(w_proj[e][sel[b][j]])  (SMEM row cache
// serving all 8 batches — verified pattern from R9, now single fp16)
// ============================================================================
__global__ void __launch_bounds__(256) gather_wproj_kernel(const float* __restrict__ wp) {
    __shared__ __half rh[F];   // 24576 B
    const int e = blockIdx.x;
    const int tid = threadIdx.x;
    const float* row = wp + (size_t)e * F;

    for (int f = tid; f < F; f += 256)
        rh[f] = __float2half_rn(row[f]);
    __syncthreads();

    for (int b = 0; b < BATCH; b++) {
        const int* sel = g_sel + b * KSEL;
        __half* bh = g_bc + (size_t)(b * D + e) * KSEL;
        for (int j = tid; j < KSEL; j += 256) {
            const int f = __ldg(sel + j);   // coalesced
            bh[j] = rh[f];
        }
    }
}

// ============================================================================
// HMMA GEMM: C[128(m) x 128(n)] per CTA = A_fp16[128xK] @ B_fp16[128xK]^T
// SINGLE MMA per fragment — R12 confirmed legacy mma.sync on sm_103 is
// issue-rate-bound (~512 MAC/cyc/SM): 3->2 MMAs gave exactly -1/3 of GEMM
// time. 2->1 halves it again; fp16-both-sides error ~4.2e-4 (2.4x margin).
// 8 warps = 2(m) x 4(n), warp tile 64x32, full coverage. 2-stage cp.async,
// static smem 2 x 8KB = 16KB, 2 CTAs/SM.
// XOR swizzle unit' = unit ^ ((row>>2)&1) -> conflict-free ldmatrix.
//   IS_G1: A = g_x_h [T,D], B = g_wm_h gathered via g_sel, K=D,
//          epilogue relu -> fp16 g_h [T,KSEL]
//  !IS_G1: A = g_h [T,KSEL], B = g_bc [D,KSEL] per batch, K=KSEL,
//          fp32 epilogue -> out [T,D]
// ============================================================================
#define A_TILE_B 4096
#define B_TILE_B 4096
#define STAGE_B  8192   // A 4K | B 4K

template <bool IS_G1>
__global__ void __launch_bounds__(256, 2) gemm_hmma(float* __restrict__ Of) {
    __shared__ __align__(16) char smbuf[2 * STAGE_B];   // 16 KB static
    __shared__ int selc[128];
    const uint32_t sbase = smem_to_u32(smbuf);
    const int tid = threadIdx.x;
    const int b = blockIdx.z;
    const int n0 = blockIdx.x * 128, m0 = blockIdx.y * 128;

    const int lda  = IS_G1 ? D : KSEL;
    const int ldb  = IS_G1 ? D : KSEL;
    const int Kdim = IS_G1 ? D : KSEL;

    const __half* A = IS_G1 ? (g_x_h + (size_t)b * T * D)
                            : (g_h + (size_t)b * T * KSEL);
    const __half* B = IS_G1 ? g_wm_h : (g_bc + (size_t)b * D * KSEL);

    if (IS_G1) {
        if (tid < 128) selc[tid] = g_sel[b * KSEL + n0 + tid];
        __syncthreads();
    }

    // --- cp.async slots: row r = tid>>1 (0..127), 16B unit u = tid&1 ---
    const int r = tid >> 1, u = tid & 1;
    const uint32_t soff = (uint32_t)(r * 32 + ((u ^ ((r >> 2) & 1)) << 4));
    const int gk = u * 8;
    const int arow = m0 + r;
    const int brow = IS_G1 ? selc[r] : (n0 + r);

    const int nch = Kdim / 16;

    auto load_stage = [&](int stage, int k0) {
        const uint32_t s = sbase + (uint32_t)stage * STAGE_B;
        cp_async16(s + soff, A + (size_t)arow * lda + k0 + gk);
        cp_async16(s + A_TILE_B + soff, B + (size_t)brow * ldb + k0 + gk);
        cp_commit();
    };

    // --- warp tiling: 8 warps = 2(m) x 4(n), warp tile 64x32 ---
    const int warp = tid >> 5, lane = tid & 31;
    const int wm = warp & 1;          // m base = wm*64
    const int wn = warp >> 1;         // n base = wn*32
    const int lt = lane >> 3, lri = lane & 7;

    const int a_row_l = (lt & 1) * 8 + lri;   // A matrices m0k0,m8k0,m0k8,m8k8
    const int a_ku    = lt >> 1;
    const int b_row_l = (lt >> 1) * 8 + lri;  // B matrices n0k0,n0k8,n8k0,n8k8
    const int b_ku    = lt & 1;

    uint32_t aoff[4];
    #pragma unroll
    for (int mi = 0; mi < 4; mi++) {
        const int ar = wm * 64 + mi * 16 + a_row_l;
        aoff[mi] = (uint32_t)(ar * 32 + ((a_ku ^ ((ar >> 2) & 1)) << 4));
    }
    uint32_t boff[2];
    #pragma unroll
    for (int g = 0; g < 2; g++) {
        const int br = wn * 32 + g * 16 + b_row_l;
        boff[g] = (uint32_t)(A_TILE_B + br * 32 + ((b_ku ^ ((br >> 2) & 1)) << 4));
    }

    float acc[4][4][4];
    #pragma unroll
    for (int mi = 0; mi < 4; mi++)
        #pragma unroll
        for (int ni = 0; ni < 4; ni++)
            #pragma unroll
            for (int q = 0; q < 4; q++) acc[mi][ni][q] = 0.f;

    load_stage(0, 0);

    for (int ch = 0; ch < nch; ch++) {
        cp_wait0();
        __syncthreads();   // stage-ch data visible; prior iteration's reads done
        if (ch + 1 < nch) load_stage((ch + 1) & 1, (ch + 1) * 16);

        const uint32_t s = sbase + (uint32_t)(ch & 1) * STAGE_B;
        uint32_t ah[4][4], bh[2][4];
        #pragma unroll
        for (int mi = 0; mi < 4; mi++) ldm_x4(ah[mi], s + aoff[mi]);
        #pragma unroll
        for (int g = 0; g < 2; g++) ldm_x4(bh[g], s + boff[g]);

        #pragma unroll
        for (int mi = 0; mi < 4; mi++)
            #pragma unroll
            for (int ni = 0; ni < 4; ni++) {
                const uint32_t* ph = &bh[ni >> 1][(ni & 1) * 2];
                mma_f16(acc[mi][ni], ah[mi], ph);
            }
    }

    // --- epilogue ---
    const int erow = lane >> 2, ecol = (lane & 3) * 2;
    #pragma unroll
    for (int mi = 0; mi < 4; mi++)
        #pragma unroll
        for (int ni = 0; ni < 4; ni++) {
            const int row = m0 + wm * 64 + mi * 16 + erow;
            const int col = n0 + wn * 32 + ni * 8 + ecol;
            #pragma unroll
            for (int h = 0; h < 2; h++) {   // c0/c1 at row, c2/c3 at row+8
                const int rr = row + h * 8;
                float f0 = acc[mi][ni][h * 2 + 0];
                float f1 = acc[mi][ni][h * 2 + 1];
                if (IS_G1) {
                    f0 = fmaxf(f0, 0.f); f1 = fmaxf(f1, 0.f);
                    const __half2 hp = __floats2half2_rn(f0, f1);
                    __half* hh = g_h + (size_t)b * T * KSEL;
                    *(uint32_t*)(hh + (size_t)rr * KSEL + col) = half2_as_u32(hp);
                } else {
                    float2 v; v.x = f0; v.y = f1;
                    *(float2*)(Of + ((size_t)b * T + rr) * D + col) = v;
                }
            }
        }
}

// ============================================================================
extern "C" void kernel_launch(void* const* d_in, const int* in_sizes, int n_in,
                              void* d_out, int out_size) {
    const float* x      = (const float*)d_in[0];
    const float* w1     = (const float*)d_in[1];
    const float* w2     = (const float*)d_in[2];
    const float* w_mfc  = (const float*)d_in[3];
    const float* w_proj = (const float*)d_in[4];
    float* out = (float*)d_out;

    pool_partial_kernel<<<BATCH * NPART, 256>>>(x);
    ck_kernel<<<BATCH, 1024>>>(w1, w2);
    topk_kernel<<<BATCH, 1024>>>();
    conv_x_kernel<<<(BATCH * T * D / 4 + 255) / 256, 256>>>(x);
    conv_wm_kernel<<<(F * D / 4 + 255) / 256, 256>>>(w_mfc);
    gather_wproj_kernel<<<D, 256>>>(w_proj);

    // GEMM1: h = relu(x_fp16 @ wm_fp16_sel^T), relu -> fp16 h
    gemm_hmma<true><<<dim3(KSEL / 128, T / 128, BATCH), 256>>>(nullptr);

    // GEMM2: out = h_fp16 @ bc_fp16^T, fp32 epilogue
    gemm_hmma<false><<<dim3(D / 128, T / 128, BATCH), 256>>>(out);
}

// round 14
// speedup vs baseline: 1.7100x; 1.0739x over previous
#include <cuda_runtime.h>
#include <cuda_bf16.h>
#include <cuda_fp16.h>
#include <cstdint>

#define BATCH 8
#define T 1024
#define D 768
#define F 12288
#define CDIM 48
#define KSEL 3072

// -------- device scratch (allocation-free rule: static __device__ globals) ----
// RULE (hard-learned R3-R7): referenced ONLY from device code. Passing these as
// host-side kernel args yields the host shadow address -> crash (rel_err 1.0).
__device__ float g_ck[BATCH * F];
__device__ int   g_sel[BATCH * KSEL];
__device__ __align__(16) __half g_x_h[(size_t)BATCH * T * D];     // fp16(x)
__device__ __align__(16) __half g_wm_h[(size_t)F * D];            // fp16(w_mfc)
__device__ __align__(16) __half g_h[(size_t)BATCH * T * KSEL];    // fp16(relu(h))
__device__ __align__(16) __half g_bc[(size_t)BATCH * D * KSEL];   // fp16 gathered w_proj

// ============================================================================
// PTX helpers (base-target only: cp.async / ldmatrix / mma.sync)
// ============================================================================
__device__ __forceinline__ uint32_t smem_to_u32(const void* p) {
    uint32_t a;
    asm("{ .reg .u64 t; cvta.to.shared.u64 t, %1; cvt.u32.u64 %0, t; }" : "=r"(a) : "l"(p));
    return a;
}
__device__ __forceinline__ void cp_async16(uint32_t saddr, const void* gptr) {
    asm volatile("cp.async.cg.shared.global [%0], [%1], 16;" :: "r"(saddr), "l"(gptr) : "memory");
}
__device__ __forceinline__ void cp_commit() { asm volatile("cp.async.commit_group;" ::: "memory"); }
__device__ __forceinline__ void cp_wait2()  { asm volatile("cp.async.wait_group 2;" ::: "memory"); }

__device__ __forceinline__ void ldm_x4(uint32_t* r, uint32_t addr) {
    asm volatile("ldmatrix.sync.aligned.m8n8.x4.shared.b16 {%0,%1,%2,%3}, [%4];"
                 : "=r"(r[0]), "=r"(r[1]), "=r"(r[2]), "=r"(r[3]) : "r"(addr));
}
__device__ __forceinline__ void mma_f16(float* c, const uint32_t* a, const uint32_t* b) {
    asm volatile("mma.sync.aligned.m16n8k16.row.col.f32.f16.f16.f32 "
                 "{%0,%1,%2,%3}, {%4,%5,%6,%7}, {%8,%9}, {%0,%1,%2,%3};"
                 : "+f"(c[0]), "+f"(c[1]), "+f"(c[2]), "+f"(c[3])
                 : "r"(a[0]), "r"(a[1]), "r"(a[2]), "r"(a[3]), "r"(b[0]), "r"(b[1]));
}
__device__ __forceinline__ uint32_t half2_as_u32(__half2 v) {
    return *reinterpret_cast<uint32_t*>(&v);
}

// ============================================================================
// K1 (fused pool+ck): pooled = mean_t x[b]; ck = relu(pooled@w1^T)@w2^T
// grid = BATCH, block = 1024. Threads 0..D-1 each own one d (coalesced).
// Same fp32 math as the verified two-kernel version -> identical top-k set.
// ============================================================================
__global__ void __launch_bounds__(1024) pool_ck_kernel(const float* __restrict__ x,
                                                       const float* __restrict__ w1,
                                                       const float* __restrict__ w2) {
    const int b = blockIdx.x;
    __shared__ float pooled_s[D];
    __shared__ float tmp_s[CDIM];
    const int tid = threadIdx.x;

    if (tid < D) {
        const float* xb = x + (size_t)b * T * D + tid;
        float s = 0.f;
        #pragma unroll 8
        for (int t = 0; t < T; t++) s += xb[(size_t)t * D];
        pooled_s[tid] = s * (1.0f / (float)T);
    }
    __syncthreads();

    const int wid = tid >> 5, lane = tid & 31;
    for (int c = wid; c < CDIM; c += 32) {
        float s = 0.f;
        for (int d = lane; d < D; d += 32) s += pooled_s[d] * w1[(size_t)c * D + d];
        #pragma unroll
        for (int o = 16; o > 0; o >>= 1) s += __shfl_xor_sync(0xFFFFFFFFu, s, o);
        if (lane == 0) tmp_s[c] = fmaxf(s, 0.f);
    }
    __syncthreads();

    for (int f = tid; f < F; f += blockDim.x) {
        const float* w2r = w2 + (size_t)f * CDIM;
        float s = 0.f;
        #pragma unroll
        for (int c = 0; c < CDIM; c++) s += tmp_s[c] * w2r[c];
        g_ck[b * F + f] = s;
    }
}

// ============================================================================
// K2: exact top-KSEL radix select + deterministic compaction (verified)
// ============================================================================
__global__ void __launch_bounds__(1024) topk_kernel() {
    const int b = blockIdx.x;
    const float* ck = g_ck + b * F;

    __shared__ unsigned hist[256];
    __shared__ unsigned s_prefix, s_remaining;
    __shared__ int s_wcnt_gt[32], s_wcnt_eq[32];
    __shared__ int s_woff_gt[32], s_woff_eq[32];
    __shared__ int s_base_gt, s_base_eq;

    const int tid = threadIdx.x;
    unsigned keys[12];
    #pragma unroll
    for (int i = 0; i < 12; i++) {
        unsigned u = __float_as_uint(ck[i * 1024 + tid]);
        keys[i] = (u & 0x80000000u) ? ~u : (u | 0x80000000u);
    }
    if (tid == 0) { s_prefix = 0u; s_remaining = KSEL; }
    unsigned prefix_mask = 0u;
    __syncthreads();

    for (int pass = 0; pass < 4; pass++) {
        const int shift = 24 - 8 * pass;
        if (tid < 256) hist[tid] = 0u;
        __syncthreads();
        const unsigned prefix = s_prefix;
        #pragma unroll
        for (int i = 0; i < 12; i++) {
            if ((keys[i] & prefix_mask) == prefix)
                atomicAdd(&hist[(keys[i] >> shift) & 255u], 1u);
        }
        __syncthreads();
        if (tid == 0) {
            const unsigned rem = s_remaining;
            unsigned cum = 0u;
            int bin = 255;
            for (; bin > 0; bin--) {
                if (cum + hist[bin] >= rem) break;
                cum += hist[bin];
            }
            s_remaining = rem - cum;
            s_prefix = prefix | ((unsigned)bin << shift);
        }
        prefix_mask |= (0xFFu << shift);
        __syncthreads();
    }

    const unsigned thr = s_prefix;
    const int remaining = (int)s_remaining;
    const int gt_total  = KSEL - remaining;

    if (tid == 0) { s_base_gt = 0; s_base_eq = 0; }
    __syncthreads();

    const int wid = tid >> 5, lane = tid & 31;
    const unsigned lmask = (1u << lane) - 1u;
    for (int i = 0; i < 12; i++) {
        const int idx = i * 1024 + tid;
        const unsigned k = keys[i];
        const bool isgt = (k > thr);
        const bool iseq = (k == thr);
        const unsigned bg = __ballot_sync(0xFFFFFFFFu, isgt);
        const unsigned be = __ballot_sync(0xFFFFFFFFu, iseq);
        if (lane == 0) { s_wcnt_gt[wid] = __popc(bg); s_wcnt_eq[wid] = __popc(be); }
        __syncthreads();
        if (tid == 0) {
            int sg = s_base_gt, se = s_base_eq;
            for (int w = 0; w < 32; w++) {
                s_woff_gt[w] = sg; sg += s_wcnt_gt[w];
                s_woff_eq[w] = se; se += s_wcnt_eq[w];
            }
            s_base_gt = sg; s_base_eq = se;
        }
        __syncthreads();
        if (isgt) {
            const int pos = s_woff_gt[wid] + __popc(bg & lmask);
            g_sel[b * KSEL + pos] = idx;
        } else if (iseq) {
            const int er = s_woff_eq[wid] + __popc(be & lmask);
            if (er < remaining) g_sel[b * KSEL + gt_total + er] = idx;
        }
    }
}

// ============================================================================
// K3 (fused convert): x -> fp16 AND w_mfc -> fp16 in one launch
// ============================================================================
#define N4X (BATCH * T * D / 4)
#define N4W (F * D / 4)
__global__ void conv_kernel(const float* __restrict__ x, const float* __restrict__ wm) {
    const int i = blockIdx.x * blockDim.x + threadIdx.x;
    if (i < N4X) {
        const float4 v = ((const float4*)x)[i];
        ((__half2*)g_x_h)[2 * i]     = __floats2half2_rn(v.x, v.y);
        ((__half2*)g_x_h)[2 * i + 1] = __floats2half2_rn(v.z, v.w);
    } else if (i < N4X + N4W) {
        const int j = i - N4X;
        const float4 v = ((const float4*)wm)[j];
        ((__half2*)g_wm_h)[2 * j]     = __floats2half2_rn(v.x, v.y);
        ((__half2*)g_wm_h)[2 * j + 1] = __floats2half2_rn(v.z, v.w);
    }
}

// ============================================================================
// K5: gather bc[b][e][j] = fp16(w_proj[e][sel[b][j]])  (SMEM row cache
// serving all 8 batches — verified)
// ============================================================================
__global__ void __launch_bounds__(256) gather_wproj_kernel(const float* __restrict__ wp) {
    __shared__ __half rh[F];   // 24576 B
    const int e = blockIdx.x;
    const int tid = threadIdx.x;
    const float* row = wp + (size_t)e * F;

    for (int f = tid; f < F; f += 256)
        rh[f] = __float2half_rn(row[f]);
    __syncthreads();

    for (int b = 0; b < BATCH; b++) {
        const int* sel = g_sel + b * KSEL;
        __half* bh = g_bc + (size_t)(b * D + e) * KSEL;
        for (int j = tid; j < KSEL; j += 256) {
            const int f = __ldg(sel + j);   // coalesced
            bh[j] = rh[f];
        }
    }
}

// ============================================================================
// HMMA GEMM: C[128(m) x 128(n)] per CTA = A_fp16[128xK] @ B_fp16[128xK]^T
// Single MMA per fragment (fp16 both sides, R13-verified, rel_err 4.1e-4).
// R13 lesson: at 1 MMA/fragment, compute/chunk (~150cyc) << load/chunk
// (~600cyc), and the 2-stage wait0 pipeline exposed ~370us of load stalls.
// Fix: 4-STAGE pipeline, wait_group 2 -> THREE chunk-loads in flight under
// every compute. Static smem 4 x 8KB = 32KB (no attribute), 2 CTAs/SM.
// Tail: empty commit_group keeps wait_group numbering sound (without it the
// last 2 chunks would be readable before their loads complete).
// XOR swizzle unit' = unit ^ ((row>>2)&1) -> conflict-free ldmatrix.
//   IS_G1: A = g_x_h [T,D], B = g_wm_h gathered via g_sel, K=D,
//          epilogue relu -> fp16 g_h [T,KSEL]
//  !IS_G1: A = g_h [T,KSEL], B = g_bc [D,KSEL] per batch, K=KSEL,
//          fp32 epilogue -> out [T,D]
// ============================================================================
#define A_TILE_B 4096
#define B_TILE_B 4096
#define STAGE_B  8192   // A 4K | B 4K
#define NSTAGE   4

template <bool IS_G1>
__global__ void __launch_bounds__(256, 2) gemm_hmma(float* __restrict__ Of) {
    __shared__ __align__(16) char smbuf[NSTAGE * STAGE_B];   // 32 KB static
    __shared__ int selc[128];
    const uint32_t sbase = smem_to_u32(smbuf);
    const int tid = threadIdx.x;
    const int b = blockIdx.z;
    const int n0 = blockIdx.x * 128, m0 = blockIdx.y * 128;

    const int lda  = IS_G1 ? D : KSEL;
    const int ldb  = IS_G1 ? D : KSEL;
    const int Kdim = IS_G1 ? D : KSEL;

    const __half* A = IS_G1 ? (g_x_h + (size_t)b * T * D)
                            : (g_h + (size_t)b * T * KSEL);
    const __half* B = IS_G1 ? g_wm_h : (g_bc + (size_t)b * D * KSEL);

    if (IS_G1) {
        if (tid < 128) selc[tid] = g_sel[b * KSEL + n0 + tid];
        __syncthreads();
    }

    // --- cp.async slots: row r = tid>>1 (0..127), 16B unit u = tid&1 ---
    const int r = tid >> 1, u = tid & 1;
    const uint32_t soff = (uint32_t)(r * 32 + ((u ^ ((r >> 2) & 1)) << 4));
    const int gk = u * 8;
    const int arow = m0 + r;
    const int brow = IS_G1 ? selc[r] : (n0 + r);

    const int nch = Kdim / 16;

    auto load_stage = [&](int stage, int k0) {
        const uint32_t s = sbase + (uint32_t)stage * STAGE_B;
        cp_async16(s + soff, A + (size_t)arow * lda + k0 + gk);
        cp_async16(s + A_TILE_B + soff, B + (size_t)brow * ldb + k0 + gk);
        cp_commit();
    };

    // --- warp tiling: 8 warps = 2(m) x 4(n), warp tile 64x32 ---
    const int warp = tid >> 5, lane = tid & 31;
    const int wm = warp & 1;          // m base = wm*64
    const int wn = warp >> 1;         // n base = wn*32
    const int lt = lane >> 3, lri = lane & 7;

    const int a_row_l = (lt & 1) * 8 + lri;   // A matrices m0k0,m8k0,m0k8,m8k8
    const int a_ku    = lt >> 1;
    const int b_row_l = (lt >> 1) * 8 + lri;  // B matrices n0k0,n0k8,n8k0,n8k8
    const int b_ku    = lt & 1;

    uint32_t aoff[4];
    #pragma unroll
    for (int mi = 0; mi < 4; mi++) {
        const int ar = wm * 64 + mi * 16 + a_row_l;
        aoff[mi] = (uint32_t)(ar * 32 + ((a_ku ^ ((ar >> 2) & 1)) << 4));
    }
    uint32_t boff[2];
    #pragma unroll
    for (int g = 0; g < 2; g++) {
        const int br = wn * 32 + g * 16 + b_row_l;
        boff[g] = (uint32_t)(A_TILE_B + br * 32 + ((b_ku ^ ((br >> 2) & 1)) << 4));
    }

    float acc[4][4][4];
    #pragma unroll
    for (int mi = 0; mi < 4; mi++)
        #pragma unroll
        for (int ni = 0; ni < 4; ni++)
            #pragma unroll
            for (int q = 0; q < 4; q++) acc[mi][ni][q] = 0.f;

    load_stage(0, 0);
    load_stage(1, 16);
    load_stage(2, 32);

    for (int ch = 0; ch < nch; ch++) {
        cp_wait2();        // stage ch complete (<=2 newer groups in flight)
        __syncthreads();   // stage-ch data visible; stage (ch+3)%4 reads done
        if (ch + 3 < nch) load_stage((ch + 3) % NSTAGE, (ch + 3) * 16);
        else cp_commit();  // empty group keeps wait_group numbering sound

        const uint32_t s = sbase + (uint32_t)(ch % NSTAGE) * STAGE_B;
        uint32_t ah[4][4], bh[2][4];
        #pragma unroll
        for (int mi = 0; mi < 4; mi++) ldm_x4(ah[mi], s + aoff[mi]);
        #pragma unroll
        for (int g = 0; g < 2; g++) ldm_x4(bh[g], s + boff[g]);

        #pragma unroll
        for (int mi = 0; mi < 4; mi++)
            #pragma unroll
            for (int ni = 0; ni < 4; ni++) {
                const uint32_t* ph = &bh[ni >> 1][(ni & 1) * 2];
                mma_f16(acc[mi][ni], ah[mi], ph);
            }
    }

    // --- epilogue ---
    const int erow = lane >> 2, ecol = (lane & 3) * 2;
    #pragma unroll
    for (int mi = 0; mi < 4; mi++)
        #pragma unroll
        for (int ni = 0; ni < 4; ni++) {
            const int row = m0 + wm * 64 + mi * 16 + erow;
            const int col = n0 + wn * 32 + ni * 8 + ecol;
            #pragma unroll
            for (int h = 0; h < 2; h++) {   // c0/c1 at row, c2/c3 at row+8
                const int rr = row + h * 8;
                float f0 = acc[mi][ni][h * 2 + 0];
                float f1 = acc[mi][ni][h * 2 + 1];
                if (IS_G1) {
                    f0 = fmaxf(f0, 0.f); f1 = fmaxf(f1, 0.f);
                    const __half2 hp = __floats2half2_rn(f0, f1);
                    __half* hh = g_h + (size_t)b * T * KSEL;
                    *(uint32_t*)(hh + (size_t)rr * KSEL + col) = half2_as_u32(hp);
                } else {
                    float2 v; v.x = f0; v.y = f1;
                    *(float2*)(Of + ((size_t)b * T + rr) * D + col) = v;
                }
            }
        }
}

// ============================================================================
extern "C" void kernel_launch(void* const* d_in, const int* in_sizes, int n_in,
                              void* d_out, int out_size) {
    const float* x      = (const float*)d_in[0];
    const float* w1     = (const float*)d_in[1];
    const float* w2     = (const float*)d_in[2];
    const float* w_mfc  = (const float*)d_in[3];
    const float* w_proj = (const float*)d_in[4];
    float* out = (float*)d_out;

    // Launch order puts gemm1 4th: ncu has captured the 4th launch every
    // round, so next round's profile shows the GEMM instead of a converter.
    pool_ck_kernel<<<BATCH, 1024>>>(x, w1, w2);                       // 1
    topk_kernel<<<BATCH, 1024>>>();                                   // 2
    conv_kernel<<<(N4X + N4W + 255) / 256, 256>>>(x, w_mfc);          // 3
    gemm_hmma<true><<<dim3(KSEL / 128, T / 128, BATCH), 256>>>(nullptr);  // 4
    gather_wproj_kernel<<<D, 256>>>(w_proj);                          // 5
    gemm_hmma<false><<<dim3(D / 128, T / 128, BATCH), 256>>>(out);    // 6
}

// round 15
// speedup vs baseline: 1.7343x; 1.0142x over previous
#include <cuda_runtime.h>
#include <cuda_bf16.h>
#include <cuda_fp16.h>
#include <cstdint>

#define BATCH 8
#define T 1024
#define D 768
#define F 12288
#define CDIM 48
#define KSEL 3072
#define NPART 16
#define TCHUNK (T / NPART)

// -------- device scratch (allocation-free rule: static __device__ globals) ----
// RULE (hard-learned R3-R7): referenced ONLY from device code. Passing these as
// host-side kernel args yields the host shadow address -> crash (rel_err 1.0).
__device__ float g_part[BATCH * NPART * D];
__device__ int   g_sel[BATCH * KSEL];
__device__ __align__(16) __half g_x_h[(size_t)BATCH * T * D];     // fp16(x)
__device__ __align__(16) __half g_wm_h[(size_t)F * D];            // fp16(w_mfc)
__device__ __align__(16) __half g_h[(size_t)BATCH * T * KSEL];    // fp16(relu(h))
__device__ __align__(16) __half g_bc[(size_t)BATCH * D * KSEL];   // fp16 gathered w_proj

// ============================================================================
// PTX helpers (base-target only: cp.async / ldmatrix / mma.sync)
// ============================================================================
__device__ __forceinline__ uint32_t smem_to_u32(const void* p) {
    uint32_t a;
    asm("{ .reg .u64 t; cvta.to.shared.u64 t, %1; cvt.u32.u64 %0, t; }" : "=r"(a) : "l"(p));
    return a;
}
__device__ __forceinline__ void cp_async16(uint32_t saddr, const void* gptr) {
    asm volatile("cp.async.cg.shared.global [%0], [%1], 16;" :: "r"(saddr), "l"(gptr) : "memory");
}
__device__ __forceinline__ void cp_commit() { asm volatile("cp.async.commit_group;" ::: "memory"); }
__device__ __forceinline__ void cp_wait1()  { asm volatile("cp.async.wait_group 1;" ::: "memory"); }

__device__ __forceinline__ void ldm_x4(uint32_t* r, uint32_t addr) {
    asm volatile("ldmatrix.sync.aligned.m8n8.x4.shared.b16 {%0,%1,%2,%3}, [%4];"
                 : "=r"(r[0]), "=r"(r[1]), "=r"(r[2]), "=r"(r[3]) : "r"(addr));
}
__device__ __forceinline__ void mma_f16(float* c, const uint32_t* a, const uint32_t* b) {
    asm volatile("mma.sync.aligned.m16n8k16.row.col.f32.f16.f16.f32 "
                 "{%0,%1,%2,%3}, {%4,%5,%6,%7}, {%8,%9}, {%0,%1,%2,%3};"
                 : "+f"(c[0]), "+f"(c[1]), "+f"(c[2]), "+f"(c[3])
                 : "r"(a[0]), "r"(a[1]), "r"(a[2]), "r"(a[3]), "r"(b[0]), "r"(b[1]));
}
__device__ __forceinline__ uint32_t half2_as_u32(__half2 v) {
    return *reinterpret_cast<uint32_t*>(&v);
}

// ============================================================================
// K2: partial sequence-mean pool (verified R1; 128 blocks — R13's 8-block
// fused version was bandwidth-starved, ~50us)
// ============================================================================
__global__ void pool_partial_kernel(const float* __restrict__ x) {
    const int b = blockIdx.x >> 4;
    const int s = blockIdx.x & 15;
    const float* xp = x + ((size_t)b * T + (size_t)s * TCHUNK) * D;
    for (int d = threadIdx.x; d < D; d += blockDim.x) {
        float acc = 0.f;
        #pragma unroll 4
        for (int t = 0; t < TCHUNK; t++) acc += xp[(size_t)t * D + d];
        g_part[(size_t)blockIdx.x * D + d] = acc;
    }
}

// ============================================================================
// K3 (fused ck+topk): per batch, compute ck = relu(pooled@w1^T)@w2^T into
// registers (same fp32 math/order as the verified split version -> identical
// top-k set), then exact radix select + deterministic compaction (verified).
// grid = BATCH, block = 1024.
// ============================================================================
__global__ void __launch_bounds__(1024) ck_topk_kernel(const float* __restrict__ w1,
                                                       const float* __restrict__ w2) {
    const int b = blockIdx.x;
    const int tid = threadIdx.x;

    __shared__ float pooled_s[D];
    __shared__ float tmp_s[CDIM];
    __shared__ unsigned hist[256];
    __shared__ unsigned s_prefix, s_remaining;
    __shared__ int s_wcnt_gt[32], s_wcnt_eq[32];
    __shared__ int s_woff_gt[32], s_woff_eq[32];
    __shared__ int s_base_gt, s_base_eq;

    // pooled mean from partials (same math as verified ck_kernel)
    for (int d = tid; d < D; d += blockDim.x) {
        float s = 0.f;
        #pragma unroll
        for (int p = 0; p < NPART; p++) s += g_part[(size_t)(b * NPART + p) * D + d];
        pooled_s[d] = s * (1.0f / (float)T);
    }
    __syncthreads();

    // tmp = relu(pooled @ w1^T): one warp per channel
    const int wid = tid >> 5, lane = tid & 31;
    for (int c = wid; c < CDIM; c += 32) {
        float s = 0.f;
        for (int d = lane; d < D; d += 32) s += pooled_s[d] * w1[(size_t)c * D + d];
        #pragma unroll
        for (int o = 16; o > 0; o >>= 1) s += __shfl_xor_sync(0xFFFFFFFFu, s, o);
        if (lane == 0) tmp_s[c] = fmaxf(s, 0.f);
    }
    __syncthreads();

    // ck -> order-preserving uint keys, held in registers
    unsigned keys[12];
    #pragma unroll
    for (int i = 0; i < 12; i++) {
        const int f = i * 1024 + tid;
        const float* w2r = w2 + (size_t)f * CDIM;
        float s = 0.f;
        #pragma unroll
        for (int c = 0; c < CDIM; c++) s += tmp_s[c] * w2r[c];
        const unsigned u = __float_as_uint(s);
        keys[i] = (u & 0x80000000u) ? ~u : (u | 0x80000000u);
    }

    if (tid == 0) { s_prefix = 0u; s_remaining = KSEL; }
    unsigned prefix_mask = 0u;
    __syncthreads();

    for (int pass = 0; pass < 4; pass++) {
        const int shift = 24 - 8 * pass;
        if (tid < 256) hist[tid] = 0u;
        __syncthreads();
        const unsigned prefix = s_prefix;
        #pragma unroll
        for (int i = 0; i < 12; i++) {
            if ((keys[i] & prefix_mask) == prefix)
                atomicAdd(&hist[(keys[i] >> shift) & 255u], 1u);
        }
        __syncthreads();
        if (tid == 0) {
            const unsigned rem = s_remaining;
            unsigned cum = 0u;
            int bin = 255;
            for (; bin > 0; bin--) {
                if (cum + hist[bin] >= rem) break;
                cum += hist[bin];
            }
            s_remaining = rem - cum;
            s_prefix = prefix | ((unsigned)bin << shift);
        }
        prefix_mask |= (0xFFu << shift);
        __syncthreads();
    }

    const unsigned thr = s_prefix;
    const int remaining = (int)s_remaining;
    const int gt_total  = KSEL - remaining;

    if (tid == 0) { s_base_gt = 0; s_base_eq = 0; }
    __syncthreads();

    const unsigned lmask = (1u << lane) - 1u;
    for (int i = 0; i < 12; i++) {
        const int idx = i * 1024 + tid;
        const unsigned k = keys[i];
        const bool isgt = (k > thr);
        const bool iseq = (k == thr);
        const unsigned bg = __ballot_sync(0xFFFFFFFFu, isgt);
        const unsigned be = __ballot_sync(0xFFFFFFFFu, iseq);
        if (lane == 0) { s_wcnt_gt[wid] = __popc(bg); s_wcnt_eq[wid] = __popc(be); }
        __syncthreads();
        if (tid == 0) {
            int sg = s_base_gt, se = s_base_eq;
            for (int w = 0; w < 32; w++) {
                s_woff_gt[w] = sg; sg += s_wcnt_gt[w];
                s_woff_eq[w] = se; se += s_wcnt_eq[w];
            }
            s_base_gt = sg; s_base_eq = se;
        }
        __syncthreads();
        if (isgt) {
            const int pos = s_woff_gt[wid] + __popc(bg & lmask);
            g_sel[b * KSEL + pos] = idx;
        } else if (iseq) {
            const int er = s_woff_eq[wid] + __popc(be & lmask);
            if (er < remaining) g_sel[b * KSEL + gt_total + er] = idx;
        }
    }
}

// ============================================================================
// K1 (fused convert): x -> fp16 AND w_mfc -> fp16 in one launch
// ============================================================================
#define N4X (BATCH * T * D / 4)
#define N4W (F * D / 4)
__global__ void conv_kernel(const float* __restrict__ x, const float* __restrict__ wm) {
    const int i = blockIdx.x * blockDim.x + threadIdx.x;
    if (i < N4X) {
        const float4 v = ((const float4*)x)[i];
        ((__half2*)g_x_h)[2 * i]     = __floats2half2_rn(v.x, v.y);
        ((__half2*)g_x_h)[2 * i + 1] = __floats2half2_rn(v.z, v.w);
    } else if (i < N4X + N4W) {
        const int j = i - N4X;
        const float4 v = ((const float4*)wm)[j];
        ((__half2*)g_wm_h)[2 * j]     = __floats2half2_rn(v.x, v.y);
        ((__half2*)g_wm_h)[2 * j + 1] = __floats2half2_rn(v.z, v.w);
    }
}

// ============================================================================
// K5: gather bc[b][e][j] = fp16(w_proj[e][sel[b][j]])  (SMEM row cache, verified)
// ============================================================================
__global__ void __launch_bounds__(256) gather_wproj_kernel(const float* __restrict__ wp) {
    __shared__ __half rh[F];   // 24576 B
    const int e = blockIdx.x;
    const int tid = threadIdx.x;
    const float* row = wp + (size_t)e * F;

    for (int f = tid; f < F; f += 256)
        rh[f] = __float2half_rn(row[f]);
    __syncthreads();

    for (int b = 0; b < BATCH; b++) {
        const int* sel = g_sel + b * KSEL;
        __half* bh = g_bc + (size_t)(b * D + e) * KSEL;
        for (int j = tid; j < KSEL; j += 256) {
            const int f = __ldg(sel + j);   // coalesced
            bh[j] = rh[f];
        }
    }
}

// ============================================================================
// HMMA GEMM: C[128 x 128] per CTA = A_fp16 @ B_fp16^T, 1 MMA/fragment.
// R14 profile: tensor 51.6%, L1 54.7% — both half-busy; per-chunk
// wait/barrier/ldmatrix/MMA serialization costs ~1.74x the pipe floors.
// R15 change: BK=32 chunks (two k-steps per barrier, fragment regs reused)
// -> half the barriers, double-length MMA bursts. 3 stages x 16KB = 48KB
// dynamic (+ attribute, R11-proven) + selc static; wait_group 1; 2 CTAs/SM.
// 64B-row swizzle u' = u ^ ((r>>1)&3): ldmatrix phase quads
// {u,u^1,u^2,u^3}(+4) all distinct -> conflict-free.
//   IS_G1: A = g_x_h [T,D], B = g_wm_h gathered via g_sel, K=D,
//          epilogue relu -> fp16 g_h [T,KSEL]
//  !IS_G1: A = g_h [T,KSEL], B = g_bc [D,KSEL] per batch, K=KSEL,
//          fp32 epilogue -> out [T,D]
// ============================================================================
#define A_TILE_B 8192
#define B_TILE_B 8192
#define STAGE_B  16384   // A 8K | B 8K   (128 rows x 64 B)
#define NSTAGE   3
#define GEMM_SMEM (NSTAGE * STAGE_B)   // 49152 B dynamic

template <bool IS_G1>
__global__ void __launch_bounds__(256, 2) gemm_hmma(float* __restrict__ Of) {
    extern __shared__ __align__(16) char smbuf[];
    __shared__ int selc[128];
    const uint32_t sbase = smem_to_u32(smbuf);
    const int tid = threadIdx.x;
    const int b = blockIdx.z;
    const int n0 = blockIdx.x * 128, m0 = blockIdx.y * 128;

    const int lda  = IS_G1 ? D : KSEL;
    const int ldb  = IS_G1 ? D : KSEL;
    const int Kdim = IS_G1 ? D : KSEL;

    const __half* A = IS_G1 ? (g_x_h + (size_t)b * T * D)
                            : (g_h + (size_t)b * T * KSEL);
    const __half* B = IS_G1 ? g_wm_h : (g_bc + (size_t)b * D * KSEL);

    if (IS_G1) {
        if (tid < 128) selc[tid] = g_sel[b * KSEL + n0 + tid];
        __syncthreads();
    }

    // --- cp.async slots: 2 per tile per thread. slot idx -> row=idx>>2,
    //     16B unit u=idx&3, swizzled u' = u ^ ((row>>1)&3) ---
    int arow[2], brow[2], gk[2];
    uint32_t soff[2];
    #pragma unroll
    for (int i = 0; i < 2; i++) {
        const int idx = tid + i * 256;
        const int r = idx >> 2, u = idx & 3;
        soff[i] = (uint32_t)(r * 64 + ((u ^ ((r >> 1) & 3)) << 4));
        gk[i]   = u * 8;
        arow[i] = m0 + r;
        brow[i] = IS_G1 ? selc[r] : (n0 + r);
    }

    const int nch = Kdim / 32;

    auto load_stage = [&](int stage, int k0) {
        const uint32_t s = sbase + (uint32_t)stage * STAGE_B;
        #pragma unroll
        for (int i = 0; i < 2; i++) {
            cp_async16(s + soff[i], A + (size_t)arow[i] * lda + k0 + gk[i]);
            cp_async16(s + A_TILE_B + soff[i], B + (size_t)brow[i] * ldb + k0 + gk[i]);
        }
        cp_commit();
    };

    // --- warp tiling: 8 warps = 2(m) x 4(n), warp tile 64x32 ---
    const int warp = tid >> 5, lane = tid & 31;
    const int wm = warp & 1;          // m base = wm*64
    const int wn = warp >> 1;         // n base = wn*32
    const int lt = lane >> 3, lri = lane & 7;

    const int a_row_l = (lt & 1) * 8 + lri;   // A matrices m0k0,m8k0,m0k8,m8k8
    const int a_ku    = lt >> 1;              // k-unit within k-step (0/1)
    const int b_row_l = (lt >> 1) * 8 + lri;  // B matrices n0k0,n0k8,n8k0,n8k8
    const int b_ku    = lt & 1;

    // per-fragment row base + row-swizzle (unit applied per k-step below)
    uint32_t a_base[4]; int a_sw[4];
    #pragma unroll
    for (int mi = 0; mi < 4; mi++) {
        const int ar = wm * 64 + mi * 16 + a_row_l;
        a_base[mi] = (uint32_t)(ar * 64);
        a_sw[mi]   = (ar >> 1) & 3;
    }
    uint32_t b_base[2]; int b_sw[2];
    #pragma unroll
    for (int g = 0; g < 2; g++) {
        const int br = wn * 32 + g * 16 + b_row_l;
        b_base[g] = (uint32_t)(A_TILE_B + br * 64);
        b_sw[g]   = (br >> 1) & 3;
    }

    float acc[4][4][4];
    #pragma unroll
    for (int mi = 0; mi < 4; mi++)
        #pragma unroll
        for (int ni = 0; ni < 4; ni++)
            #pragma unroll
            for (int q = 0; q < 4; q++) acc[mi][ni][q] = 0.f;

    load_stage(0, 0);
    load_stage(1, 32);

    for (int ch = 0; ch < nch; ch++) {
        cp_wait1();        // stage ch complete (one newer group may stay in flight)
        __syncthreads();   // stage-ch data visible; stage (ch+2)%3 reads done
        if (ch + 2 < nch) load_stage((ch + 2) % NSTAGE, (ch + 2) * 32);
        else cp_commit();  // empty group keeps wait_group numbering sound

        const uint32_t s = sbase + (uint32_t)(ch % NSTAGE) * STAGE_B;
        #pragma unroll
        for (int ks = 0; ks < 2; ks++) {
            uint32_t ah[4][4], bh[2][4];
            #pragma unroll
            for (int mi = 0; mi < 4; mi++) {
                const uint32_t u = (uint32_t)(((ks << 1) + a_ku) ^ a_sw[mi]) << 4;
                ldm_x4(ah[mi], s + a_base[mi] + u);
            }
            #pragma unroll
            for (int g = 0; g < 2; g++) {
                const uint32_t u = (uint32_t)(((ks << 1) + b_ku) ^ b_sw[g]) << 4;
                ldm_x4(bh[g], s + b_base[g] + u);
            }
            #pragma unroll
            for (int mi = 0; mi < 4; mi++)
                #pragma unroll
                for (int ni = 0; ni < 4; ni++) {
                    const uint32_t* ph = &bh[ni >> 1][(ni & 1) * 2];
                    mma_f16(acc[mi][ni], ah[mi], ph);
                }
        }
    }

    // --- epilogue ---
    const int erow = lane >> 2, ecol = (lane & 3) * 2;
    #pragma unroll
    for (int mi = 0; mi < 4; mi++)
        #pragma unroll
        for (int ni = 0; ni < 4; ni++) {
            const int row = m0 + wm * 64 + mi * 16 + erow;
            const int col = n0 + wn * 32 + ni * 8 + ecol;
            #pragma unroll
            for (int h = 0; h < 2; h++) {   // c0/c1 at row, c2/c3 at row+8
                const int rr = row + h * 8;
                float f0 = acc[mi][ni][h * 2 + 0];
                float f1 = acc[mi][ni][h * 2 + 1];
                if (IS_G1) {
                    f0 = fmaxf(f0, 0.f); f1 = fmaxf(f1, 0.f);
                    const __half2 hp = __floats2half2_rn(f0, f1);
                    __half* hh = g_h + (size_t)b * T * KSEL;
                    *(uint32_t*)(hh + (size_t)rr * KSEL + col) = half2_as_u32(hp);
                } else {
                    float2 v; v.x = f0; v.y = f1;
                    *(float2*)(Of + ((size_t)b * T + rr) * D + col) = v;
                }
            }
        }
}

// ============================================================================
extern "C" void kernel_launch(void* const* d_in, const int* in_sizes, int n_in,
                              void* d_out, int out_size) {
    const float* x      = (const float*)d_in[0];
    const float* w1     = (const float*)d_in[1];
    const float* w2     = (const float*)d_in[2];
    const float* w_mfc  = (const float*)d_in[3];
    const float* w_proj = (const float*)d_in[4];
    float* out = (float*)d_out;

    // >48KB-adjacent dynamic SMEM opt-in (49152 dynamic + 512 static selc;
    // R10 lesson). Host attribute call: capture-neutral, R11-proven.
    static bool attr_done = false;
    if (!attr_done) {
        cudaFuncSetAttribute(gemm_hmma<true>,
                             cudaFuncAttributeMaxDynamicSharedMemorySize, GEMM_SMEM);
        cudaFuncSetAttribute(gemm_hmma<false>,
                             cudaFuncAttributeMaxDynamicSharedMemorySize, GEMM_SMEM);
        attr_done = true;
    }

    // gemm1 stays the 4th launch (ncu capture slot).
    conv_kernel<<<(N4X + N4W + 255) / 256, 256>>>(x, w_mfc);              // 1
    pool_partial_kernel<<<BATCH * NPART, 256>>>(x);                       // 2
    ck_topk_kernel<<<BATCH, 1024>>>(w1, w2);                              // 3
    gemm_hmma<true><<<dim3(KSEL / 128, T / 128, BATCH), 256, GEMM_SMEM>>>(nullptr); // 4
    gather_wproj_kernel<<<D, 256>>>(w_proj);                              // 5
    gemm_hmma<false><<<dim3(D / 128, T / 128, BATCH), 256, GEMM_SMEM>>>(out);       // 6
}